// round 1
// baseline (speedup 1.0000x reference)
#include <cuda_runtime.h>

#define N_NODES 100000
#define N_EDGES 1600000
#define D 128
#define DOUT 16

#define BM 64
#define BK 16
#define GEMM_THREADS 256
#define GEMM_BLOCKS ((N_NODES + BM - 1) / BM)

// ---------------- scratch (static device globals; no allocation allowed) ----
__device__ float g_agg[(size_t)N_NODES * D];   // aggregation output (both layers)
__device__ float g_h[(size_t)N_NODES * D];     // hidden activations after layer 1
__device__ int   g_cnt[N_NODES];
__device__ int   g_off[N_NODES];
__device__ int   g_cur[N_NODES];
__device__ int   g_csr[N_EDGES];

// ---------------- CSR build -------------------------------------------------
__global__ void k_zero_cnt() {
    int i = blockIdx.x * blockDim.x + threadIdx.x;
    if (i < N_NODES) g_cnt[i] = 0;
}

__global__ void k_hist(const int* __restrict__ dst) {
    for (int e = blockIdx.x * blockDim.x + threadIdx.x; e < N_EDGES;
         e += gridDim.x * blockDim.x)
        atomicAdd(&g_cnt[dst[e]], 1);
}

// single-block exclusive scan of g_cnt -> g_off (and g_cur copy)
__global__ void k_scan() {
    const int T = 1024;
    const int SEG = (N_NODES + T - 1) / T;   // 98
    int t = threadIdx.x;
    int base = t * SEG;
    int s = 0;
    for (int i = 0; i < SEG; i++) {
        int idx = base + i;
        if (idx < N_NODES) s += g_cnt[idx];
    }
    __shared__ int sh[T];
    sh[t] = s;
    __syncthreads();
    for (int off = 1; off < T; off <<= 1) {
        int v = (t >= off) ? sh[t - off] : 0;
        __syncthreads();
        sh[t] += v;
        __syncthreads();
    }
    int run = sh[t] - s;   // exclusive prefix for this thread's segment
    for (int i = 0; i < SEG; i++) {
        int idx = base + i;
        if (idx < N_NODES) {
            g_off[idx] = run;
            g_cur[idx] = run;
            run += g_cnt[idx];
        }
    }
}

__global__ void k_scatter(const int* __restrict__ src, const int* __restrict__ dst) {
    for (int e = blockIdx.x * blockDim.x + threadIdx.x; e < N_EDGES;
         e += gridDim.x * blockDim.x) {
        int d = dst[e];
        int p = atomicAdd(&g_cur[d], 1);
        g_csr[p] = src[e];
    }
}

// ---------------- mean aggregation: one warp per destination node -----------
__global__ void k_aggregate(const float* __restrict__ feat, float* __restrict__ out) {
    int warp = (blockIdx.x * blockDim.x + threadIdx.x) >> 5;
    int lane = threadIdx.x & 31;
    if (warp >= N_NODES) return;
    int off = g_off[warp];
    int deg = g_cnt[warp];
    float4 acc = make_float4(0.f, 0.f, 0.f, 0.f);
    const float4* f4 = (const float4*)feat;
    for (int i = 0; i < deg; i++) {
        int s = g_csr[off + i];          // broadcast read (same addr across warp)
        float4 v = f4[(size_t)s * 32 + lane];
        acc.x += v.x; acc.y += v.y; acc.z += v.z; acc.w += v.w;
    }
    float inv = 1.0f / (float)max(deg, 1);
    acc.x *= inv; acc.y *= inv; acc.z *= inv; acc.w *= inv;
    ((float4*)out)[(size_t)warp * 32 + lane] = acc;
}

// ---------------- fused dual-GEMM mainloop helper ---------------------------
// C[row,col] = sum_k A1[row,k]*W1[col,k] + sum_k A2[row,k]*W2[col,k]
// BM=64 rows x 128 cols per block, 256 threads, 8x4 outputs per thread.
__device__ __forceinline__ void gemm_mainloop(
    const float* __restrict__ A1, const float* __restrict__ A2,
    const float* __restrict__ W1, const float* __restrict__ W2,
    int rowBase, float (*As)[68], float (*Bs)[D], float acc[8][4])
{
    int tid = threadIdx.x;
    int tr = tid >> 5;            // 0..7  (warp id == thread-row group)
    int tc = tid & 31;            // 0..31 (column group of 4)
    int la_row = tid >> 2;        // 0..63
    int la_k   = (tid & 3) * 4;   // 0,4,8,12
    int lb_col = tid & 127;       // 0..127
    int lb_kg  = (tid >> 7) * 8;  // 0 or 8

    for (int phase = 0; phase < 2; phase++) {
        const float* A = phase ? A2 : A1;
        const float* W = phase ? W2 : W1;
#pragma unroll
        for (int kb = 0; kb < D; kb += BK) {
            // A tile: 64 rows x 16 k, stored transposed As[k][row]
            int grow = rowBase + la_row;
            float4 av = make_float4(0.f, 0.f, 0.f, 0.f);
            if (grow < N_NODES)
                av = *(const float4*)(A + (size_t)grow * D + kb + la_k);
            As[la_k + 0][la_row] = av.x;
            As[la_k + 1][la_row] = av.y;
            As[la_k + 2][la_row] = av.z;
            As[la_k + 3][la_row] = av.w;
            // W tile: 128 cols x 16 k, stored Bs[k][col]
            const float* wp = W + (size_t)lb_col * D + kb + lb_kg;
            float4 w0 = *(const float4*)(wp);
            float4 w1 = *(const float4*)(wp + 4);
            Bs[lb_kg + 0][lb_col] = w0.x;
            Bs[lb_kg + 1][lb_col] = w0.y;
            Bs[lb_kg + 2][lb_col] = w0.z;
            Bs[lb_kg + 3][lb_col] = w0.w;
            Bs[lb_kg + 4][lb_col] = w1.x;
            Bs[lb_kg + 5][lb_col] = w1.y;
            Bs[lb_kg + 6][lb_col] = w1.z;
            Bs[lb_kg + 7][lb_col] = w1.w;
            __syncthreads();
#pragma unroll
            for (int k = 0; k < BK; k++) {
                float4 a0 = ((const float4*)&As[k][0])[tr * 2 + 0];
                float4 a1 = ((const float4*)&As[k][0])[tr * 2 + 1];
                float4 b  = ((const float4*)&Bs[k][0])[tc];
                float ar[8] = {a0.x, a0.y, a0.z, a0.w, a1.x, a1.y, a1.z, a1.w};
                float br[4] = {b.x, b.y, b.z, b.w};
#pragma unroll
                for (int r = 0; r < 8; r++)
#pragma unroll
                    for (int c = 0; c < 4; c++)
                        acc[r][c] += ar[r] * br[c];
            }
            __syncthreads();
        }
    }
}

// ---------------- layer 1: h = relu(agg@W1l^T + x@W1r^T + b1l) --------------
__global__ __launch_bounds__(GEMM_THREADS)
void k_layer1(const float* __restrict__ A1, const float* __restrict__ A2,
              const float* __restrict__ W1, const float* __restrict__ W2,
              const float* __restrict__ bias, float* __restrict__ out)
{
    __shared__ float As[BK][68];
    __shared__ float Bs[BK][D];
    float acc[8][4];
#pragma unroll
    for (int r = 0; r < 8; r++)
#pragma unroll
        for (int c = 0; c < 4; c++) acc[r][c] = 0.f;

    int rowBase = blockIdx.x * BM;
    gemm_mainloop(A1, A2, W1, W2, rowBase, As, Bs, acc);

    int tr = threadIdx.x >> 5;
    int tc = threadIdx.x & 31;
    float4 bv = ((const float4*)bias)[tc];
#pragma unroll
    for (int r = 0; r < 8; r++) {
        int row = rowBase + tr * 8 + r;
        if (row < N_NODES) {
            float4 o;
            o.x = fmaxf(acc[r][0] + bv.x, 0.f);
            o.y = fmaxf(acc[r][1] + bv.y, 0.f);
            o.z = fmaxf(acc[r][2] + bv.z, 0.f);
            o.w = fmaxf(acc[r][3] + bv.w, 0.f);
            ((float4*)(out + (size_t)row * D))[tc] = o;
        }
    }
}

// ---------------- layer 2 + classifier --------------------------------------
// z = agg2@W2l^T + h@W2r^T + b2l ;  out = z@Wc^T + bc   (fused, no z round-trip)
__global__ __launch_bounds__(GEMM_THREADS)
void k_layer2(const float* __restrict__ A1, const float* __restrict__ A2,
              const float* __restrict__ W1, const float* __restrict__ W2,
              const float* __restrict__ bias,
              const float* __restrict__ Wc, const float* __restrict__ bc,
              float* __restrict__ out)
{
    __shared__ union {
        struct { float As[BK][68]; float Bs[BK][D]; } t;
        float Zs[BM][132];                       // padded: stride 132 (16B aligned, bank-safe)
    } sm;
    __shared__ float Wcs[DOUT][132];             // padded stride
    __shared__ float bcs[DOUT];
    __shared__ float bs[D];

    int tid = threadIdx.x;
    // preload classifier weights + biases
    for (int i = tid; i < DOUT * D; i += GEMM_THREADS)
        Wcs[i / D][i % D] = Wc[i];
    if (tid < D) bs[tid] = bias[tid];
    if (tid < DOUT) bcs[tid] = bc[tid];

    float acc[8][4];
#pragma unroll
    for (int r = 0; r < 8; r++)
#pragma unroll
        for (int c = 0; c < 4; c++) acc[r][c] = 0.f;

    int rowBase = blockIdx.x * BM;
    __syncthreads();
    gemm_mainloop(A1, A2, W1, W2, rowBase, sm.t.As, sm.t.Bs, acc);

    // stage z tile (with bias) into smem
    int tr = tid >> 5;
    int tc = tid & 31;
#pragma unroll
    for (int r = 0; r < 8; r++) {
#pragma unroll
        for (int c = 0; c < 4; c++)
            sm.Zs[tr * 8 + r][tc * 4 + c] = acc[r][c] + bs[tc * 4 + c];
    }
    __syncthreads();

    // classifier: each thread -> 1 row x 4 out-cols, dot over 128
    int zr = tid >> 2;            // 0..63
    int c4 = (tid & 3) * 4;       // 0,4,8,12
    float o[4] = {0.f, 0.f, 0.f, 0.f};
    const float4* zrow = (const float4*)&sm.Zs[zr][0];
#pragma unroll
    for (int kq = 0; kq < D / 4; kq++) {
        float4 z4 = zrow[kq];
#pragma unroll
        for (int c = 0; c < 4; c++) {
            float4 w4 = ((const float4*)&Wcs[c4 + c][0])[kq];
            o[c] += z4.x * w4.x + z4.y * w4.y + z4.z * w4.z + z4.w * w4.w;
        }
    }
    int row = rowBase + zr;
    if (row < N_NODES) {
        float4 ov = make_float4(o[0] + bcs[c4 + 0], o[1] + bcs[c4 + 1],
                                o[2] + bcs[c4 + 2], o[3] + bcs[c4 + 3]);
        *(float4*)(out + (size_t)row * DOUT + c4) = ov;
    }
}

// ---------------- launch ----------------------------------------------------
extern "C" void kernel_launch(void* const* d_in, const int* in_sizes, int n_in,
                              void* d_out, int out_size)
{
    const float* x   = (const float*)d_in[0];
    const int*   ei  = (const int*)d_in[1];     // [2, E]: row 0 = src, row 1 = dst
    const float* W1l = (const float*)d_in[2];
    const float* b1l = (const float*)d_in[3];
    const float* W1r = (const float*)d_in[4];
    const float* W2l = (const float*)d_in[5];
    const float* b2l = (const float*)d_in[6];
    const float* W2r = (const float*)d_in[7];
    const float* Wc  = (const float*)d_in[8];
    const float* bc  = (const float*)d_in[9];
    float* out = (float*)d_out;

    const int* src = ei;
    const int* dst = ei + N_EDGES;

    float *agg, *h;
    cudaGetSymbolAddress((void**)&agg, g_agg);
    cudaGetSymbolAddress((void**)&h, g_h);

    // CSR build (reused by both layers)
    k_zero_cnt<<<(N_NODES + 1023) / 1024, 1024>>>();
    k_hist<<<2048, 256>>>(dst);
    k_scan<<<1, 1024>>>();
    k_scatter<<<2048, 256>>>(src, dst);

    // layer 1
    k_aggregate<<<N_NODES / 8, 256>>>(x, agg);
    k_layer1<<<GEMM_BLOCKS, GEMM_THREADS>>>(agg, x, W1l, W1r, b1l, h);

    // layer 2 + classifier
    k_aggregate<<<N_NODES / 8, 256>>>(h, agg);
    k_layer2<<<GEMM_BLOCKS, GEMM_THREADS>>>(agg, h, W2l, W2r, b2l, Wc, bc, out);
}

// round 2
// speedup vs baseline: 1.3085x; 1.3085x over previous
#include <cuda_runtime.h>
#include <cuda_bf16.h>
#include <cstdint>

#define N_NODES 100000
#define N_EDGES 1600000
#define D 128
#define DOUT 16

#define BM 128
#define GT 256
#define GEMM_BLOCKS ((N_NODES + BM - 1) / BM)

// ---------------- scratch (static device globals) ---------------------------
__device__ float g_agg[(size_t)N_NODES * D];   // aggregation out; layer2 z in-place
__device__ float g_h[(size_t)N_NODES * D];     // hidden activations
__device__ int   g_cnt[N_NODES];
__device__ int   g_off[N_NODES];
__device__ int   g_cur[N_NODES];
__device__ int   g_csr[N_EDGES];
__device__ __nv_bfloat16 g_wh[4 * D * D];      // weight hi parts (W1l,W1r,W2l,W2r)
__device__ __nv_bfloat16 g_wl[4 * D * D];      // weight lo parts

// ---------------- helpers ---------------------------------------------------
__device__ __forceinline__ uint32_t packbf(float a, float b) {
    uint16_t ha = __bfloat16_as_ushort(__float2bfloat16_rn(a));
    uint16_t hb = __bfloat16_as_ushort(__float2bfloat16_rn(b));
    return (uint32_t)ha | ((uint32_t)hb << 16);
}
__device__ __forceinline__ float residf(float f) {
    return f - __bfloat162float(__float2bfloat16_rn(f));
}

#define LDSM4(r0, r1, r2, r3, addr)                                            \
    asm volatile("ldmatrix.sync.aligned.m8n8.x4.shared.b16 {%0,%1,%2,%3}, [%4];" \
                 : "=r"(r0), "=r"(r1), "=r"(r2), "=r"(r3) : "r"(addr))

#define MMA16816(cc, a, b0, b1)                                                \
    asm volatile("mma.sync.aligned.m16n8k16.row.col.f32.bf16.bf16.f32 "        \
                 "{%0,%1,%2,%3}, {%4,%5,%6,%7}, {%8,%9}, {%0,%1,%2,%3};"       \
                 : "+f"(cc[0]), "+f"(cc[1]), "+f"(cc[2]), "+f"(cc[3])          \
                 : "r"(a[0]), "r"(a[1]), "r"(a[2]), "r"(a[3]), "r"(b0), "r"(b1))

// ---------------- CSR build -------------------------------------------------
__global__ void k_zero_cnt() {
    int i = blockIdx.x * blockDim.x + threadIdx.x;
    if (i < N_NODES) g_cnt[i] = 0;
}

__global__ void k_hist(const int* __restrict__ dst) {
    for (int e = blockIdx.x * blockDim.x + threadIdx.x; e < N_EDGES;
         e += gridDim.x * blockDim.x)
        atomicAdd(&g_cnt[dst[e]], 1);
}

__global__ void k_scan() {
    const int T = 1024;
    const int SEG = (N_NODES + T - 1) / T;
    int t = threadIdx.x;
    int base = t * SEG;
    int s = 0;
    for (int i = 0; i < SEG; i++) {
        int idx = base + i;
        if (idx < N_NODES) s += g_cnt[idx];
    }
    __shared__ int sh[T];
    sh[t] = s;
    __syncthreads();
    for (int off = 1; off < T; off <<= 1) {
        int v = (t >= off) ? sh[t - off] : 0;
        __syncthreads();
        sh[t] += v;
        __syncthreads();
    }
    int run = sh[t] - s;
    for (int i = 0; i < SEG; i++) {
        int idx = base + i;
        if (idx < N_NODES) {
            g_off[idx] = run;
            g_cur[idx] = run;
            run += g_cnt[idx];
        }
    }
}

__global__ void k_scatter(const int* __restrict__ src, const int* __restrict__ dst) {
    for (int e = blockIdx.x * blockDim.x + threadIdx.x; e < N_EDGES;
         e += gridDim.x * blockDim.x) {
        int d = dst[e];
        int p = atomicAdd(&g_cur[d], 1);
        g_csr[p] = src[e];
    }
}

// ---------------- weight hi/lo split ----------------------------------------
__global__ void k_convw(const float* __restrict__ W1l, const float* __restrict__ W1r,
                        const float* __restrict__ W2l, const float* __restrict__ W2r) {
    int i = blockIdx.x * blockDim.x + threadIdx.x;   // 0 .. 4*16384-1
    const float* srcs[4] = {W1l, W1r, W2l, W2r};
    float v = srcs[i >> 14][i & 16383];
    __nv_bfloat16 h = __float2bfloat16_rn(v);
    g_wh[i] = h;
    g_wl[i] = __float2bfloat16_rn(v - __bfloat162float(h));
}

// ---------------- mean aggregation: one warp per destination node -----------
__global__ void k_aggregate(const float* __restrict__ feat, float* __restrict__ out) {
    int warp = (blockIdx.x * blockDim.x + threadIdx.x) >> 5;
    int lane = threadIdx.x & 31;
    if (warp >= N_NODES) return;
    int off = g_off[warp];
    int deg = g_cnt[warp];
    float4 acc = make_float4(0.f, 0.f, 0.f, 0.f);
    const float4* f4 = (const float4*)feat;
    for (int i = 0; i < deg; i++) {
        int s = g_csr[off + i];
        float4 v = f4[(size_t)s * 32 + lane];
        acc.x += v.x; acc.y += v.y; acc.z += v.z; acc.w += v.w;
    }
    float inv = 1.0f / (float)max(deg, 1);
    acc.x *= inv; acc.y *= inv; acc.z *= inv; acc.w *= inv;
    ((float4*)out)[(size_t)warp * 32 + lane] = acc;
}

// ---------------- tensor-core dual GEMM -------------------------------------
// out[row,col] = sum_k A1[row,k]*Wa[col,k] + sum_k A2[row,k]*Wb[col,k] (+bias, relu?)
// bf16 hi/lo split: 3 MMAs per logical product (drops lo*lo, err ~2^-16).
__global__ __launch_bounds__(GT, 2)
void k_gemm(const float* __restrict__ A1, const float* __restrict__ A2,
            int w1idx, int w2idx, const float* __restrict__ bias,
            float* __restrict__ out, int do_relu)
{
    // smem: rows of 16 bf16 padded to 24 (48B stride -> LDSM conflict-free)
    __shared__ __align__(16) __nv_bfloat16 sAh[BM * 24];
    __shared__ __align__(16) __nv_bfloat16 sAl[BM * 24];
    __shared__ __align__(16) __nv_bfloat16 sBh[BM * 24];
    __shared__ __align__(16) __nv_bfloat16 sBl[BM * 24];
    __shared__ float sbias[D];

    int tid  = threadIdx.x;
    int lane = tid & 31;
    int warp = tid >> 5;
    int warp_m = warp & 3;     // 4 warps along M (32 rows each)
    int warp_n = warp >> 2;    // 2 warps along N (64 cols each)
    int rowBase = blockIdx.x * BM;

    if (tid < D) sbias[tid] = bias[tid];

    // loader indices
    int lrow  = tid >> 1;        // 0..127 (row for A, col for B)
    int lhalf = tid & 1;         // which 8-element half of the 16-wide k chunk

    // LDSM source offsets (bytes)
    int ldrow = lane & 15;
    int ldoff = (lane >> 4) * 16;
    uint32_t aoff = (uint32_t)((warp_m * 32 + ldrow) * 48 + ldoff);
    uint32_t boff = (uint32_t)((warp_n * 64 + ldrow) * 48 + ldoff);
    uint32_t sAh_b = (uint32_t)__cvta_generic_to_shared(sAh);
    uint32_t sAl_b = (uint32_t)__cvta_generic_to_shared(sAl);
    uint32_t sBh_b = (uint32_t)__cvta_generic_to_shared(sBh);
    uint32_t sBl_b = (uint32_t)__cvta_generic_to_shared(sBl);

    float c[2][8][4];
#pragma unroll
    for (int mt = 0; mt < 2; mt++)
#pragma unroll
        for (int nc = 0; nc < 8; nc++)
#pragma unroll
            for (int r = 0; r < 4; r++) c[mt][nc][r] = 0.f;

    int grow = rowBase + lrow;
    bool rowOk = grow < N_NODES;

#pragma unroll 1
    for (int ph = 0; ph < 2; ph++) {
        const float* A = ph ? A2 : A1;
        const __nv_bfloat16* Wh = g_wh + (size_t)(ph ? w2idx : w1idx) * D * D;
        const __nv_bfloat16* Wl = g_wl + (size_t)(ph ? w2idx : w1idx) * D * D;

#pragma unroll 1
        for (int kb = 0; kb < D; kb += 16) {
            __syncthreads();
            // ---- A tile: load fp32, split hi/lo, store bf16 ----
            float v0 = 0.f, v1 = 0.f, v2 = 0.f, v3 = 0.f;
            float v4 = 0.f, v5 = 0.f, v6 = 0.f, v7 = 0.f;
            if (rowOk) {
                const float* ap = A + (size_t)grow * D + kb + lhalf * 8;
                float4 f0 = *(const float4*)ap;
                float4 f1 = *(const float4*)(ap + 4);
                v0 = f0.x; v1 = f0.y; v2 = f0.z; v3 = f0.w;
                v4 = f1.x; v5 = f1.y; v6 = f1.z; v7 = f1.w;
            }
            {
                uint4 h = make_uint4(packbf(v0, v1), packbf(v2, v3),
                                     packbf(v4, v5), packbf(v6, v7));
                uint4 l = make_uint4(packbf(residf(v0), residf(v1)),
                                     packbf(residf(v2), residf(v3)),
                                     packbf(residf(v4), residf(v5)),
                                     packbf(residf(v6), residf(v7)));
                *(uint4*)(sAh + lrow * 24 + lhalf * 8) = h;
                *(uint4*)(sAl + lrow * 24 + lhalf * 8) = l;
            }
            // ---- B tile: copy preconverted bf16 ----
            {
                uint4 wh = *(const uint4*)(Wh + (size_t)lrow * D + kb + lhalf * 8);
                uint4 wl = *(const uint4*)(Wl + (size_t)lrow * D + kb + lhalf * 8);
                *(uint4*)(sBh + lrow * 24 + lhalf * 8) = wh;
                *(uint4*)(sBl + lrow * 24 + lhalf * 8) = wl;
            }
            __syncthreads();

            // ---- fragments + MMAs ----
            uint32_t ah[2][4], al[2][4];
            LDSM4(ah[0][0], ah[0][1], ah[0][2], ah[0][3], sAh_b + aoff);
            LDSM4(ah[1][0], ah[1][1], ah[1][2], ah[1][3], sAh_b + aoff + 16 * 48);
            LDSM4(al[0][0], al[0][1], al[0][2], al[0][3], sAl_b + aoff);
            LDSM4(al[1][0], al[1][1], al[1][2], al[1][3], sAl_b + aoff + 16 * 48);

#pragma unroll
            for (int ng = 0; ng < 4; ng++) {
                uint32_t bh[4], bl[4];
                LDSM4(bh[0], bh[1], bh[2], bh[3], sBh_b + boff + ng * 16 * 48);
                LDSM4(bl[0], bl[1], bl[2], bl[3], sBl_b + boff + ng * 16 * 48);
#pragma unroll
                for (int mt = 0; mt < 2; mt++) {
#pragma unroll
                    for (int sub = 0; sub < 2; sub++) {
                        float* cc = c[mt][ng * 2 + sub];
                        MMA16816(cc, ah[mt], bh[sub], bh[sub + 2]);
                        MMA16816(cc, ah[mt], bl[sub], bl[sub + 2]);
                        MMA16816(cc, al[mt], bh[sub], bh[sub + 2]);
                    }
                }
            }
        }
    }
    __syncthreads();

    // ---- epilogue ----
    int g = lane >> 2;
    int q = (lane & 3) * 2;
#pragma unroll
    for (int mt = 0; mt < 2; mt++) {
        int r0 = rowBase + warp_m * 32 + mt * 16 + g;
#pragma unroll
        for (int nc = 0; nc < 8; nc++) {
            int col = warp_n * 64 + nc * 8 + q;
            float b0 = sbias[col], b1 = sbias[col + 1];
            float* cc = c[mt][nc];
            float o0 = cc[0] + b0, o1 = cc[1] + b1;
            float o2 = cc[2] + b0, o3 = cc[3] + b1;
            if (do_relu) {
                o0 = fmaxf(o0, 0.f); o1 = fmaxf(o1, 0.f);
                o2 = fmaxf(o2, 0.f); o3 = fmaxf(o3, 0.f);
            }
            if (r0 < N_NODES) {
                float2 w = make_float2(o0, o1);
                *(float2*)(out + (size_t)r0 * D + col) = w;
            }
            if (r0 + 8 < N_NODES) {
                float2 w = make_float2(o2, o3);
                *(float2*)(out + (size_t)(r0 + 8) * D + col) = w;
            }
        }
    }
}

// ---------------- classifier: out = z @ Wc^T + bc ---------------------------
__global__ __launch_bounds__(256)
void k_classifier(const float* __restrict__ z, const float* __restrict__ Wc,
                  const float* __restrict__ bc, float* __restrict__ out)
{
    __shared__ float sW[DOUT][132];
    __shared__ float sb[DOUT];
    int tid = threadIdx.x;
    for (int i = tid; i < DOUT * D; i += 256) sW[i >> 7][i & 127] = Wc[i];
    if (tid < DOUT) sb[tid] = bc[tid];
    __syncthreads();

    int col = tid & 15;
    int row = blockIdx.x * 16 + (tid >> 4);
    if (row >= N_NODES) return;
    const float4* zr = (const float4*)(z + (size_t)row * D);
    float acc = 0.f;
#pragma unroll
    for (int k = 0; k < D / 4; k++) {
        float4 zv = zr[k];
        float4 wv = *(const float4*)&sW[col][k * 4];
        acc += zv.x * wv.x + zv.y * wv.y + zv.z * wv.z + zv.w * wv.w;
    }
    out[(size_t)row * DOUT + col] = acc + sb[col];
}

// ---------------- launch ----------------------------------------------------
extern "C" void kernel_launch(void* const* d_in, const int* in_sizes, int n_in,
                              void* d_out, int out_size)
{
    const float* x   = (const float*)d_in[0];
    const int*   ei  = (const int*)d_in[1];
    const float* W1l = (const float*)d_in[2];
    const float* b1l = (const float*)d_in[3];
    const float* W1r = (const float*)d_in[4];
    const float* W2l = (const float*)d_in[5];
    const float* b2l = (const float*)d_in[6];
    const float* W2r = (const float*)d_in[7];
    const float* Wc  = (const float*)d_in[8];
    const float* bc  = (const float*)d_in[9];
    float* out = (float*)d_out;

    const int* src = ei;
    const int* dst = ei + N_EDGES;

    float *agg, *h;
    cudaGetSymbolAddress((void**)&agg, g_agg);
    cudaGetSymbolAddress((void**)&h, g_h);

    // CSR build + weight split (independent work, overlaps on stream)
    k_zero_cnt<<<(N_NODES + 1023) / 1024, 1024>>>();
    k_convw<<<(4 * D * D) / 256, 256>>>(W1l, W1r, W2l, W2r);
    k_hist<<<2048, 256>>>(dst);
    k_scan<<<1, 1024>>>();
    k_scatter<<<2048, 256>>>(src, dst);

    // layer 1
    k_aggregate<<<(N_NODES * 32 + 255) / 256, 256>>>(x, agg);
    k_gemm<<<GEMM_BLOCKS, GT>>>(agg, x, 0, 1, b1l, h, 1);

    // layer 2 (z written in-place into agg) + classifier
    k_aggregate<<<(N_NODES * 32 + 255) / 256, 256>>>(h, agg);
    k_gemm<<<GEMM_BLOCKS, GT>>>(agg, h, 2, 3, b2l, agg, 0);
    k_classifier<<<(N_NODES + 15) / 16, 256>>>(agg, Wc, bc, out);
}

// round 3
// speedup vs baseline: 1.8256x; 1.3952x over previous
#include <cuda_runtime.h>
#include <cuda_bf16.h>
#include <cstdint>

#define N_NODES 100000
#define N_EDGES 1600000
#define D 128
#define DOUT 16

#define BM 128
#define GT 256
#define GEMM_BLOCKS ((N_NODES + BM - 1) / BM)
#define SCAN_BLKS ((N_NODES + 1023) / 1024)   // 98

// ---------------- scratch (static device globals) ---------------------------
__device__ float g_agg[(size_t)N_NODES * D];   // aggregation out; layer2 z in-place
__device__ float g_h[(size_t)N_NODES * D];     // hidden activations
__device__ int   g_cnt[N_NODES];
__device__ int   g_off[N_NODES];
__device__ int   g_cur[N_NODES];
__device__ int   g_csr[N_EDGES];
__device__ int   g_blksum[SCAN_BLKS];
__device__ int   g_blkpfx[SCAN_BLKS];
__device__ __nv_bfloat16 g_wh[4 * D * D];      // weight hi parts (W1l,W1r,W2l,W2r)
__device__ __nv_bfloat16 g_wl[4 * D * D];      // weight lo parts

// ---------------- helpers ---------------------------------------------------
__device__ __forceinline__ uint32_t packbf(float a, float b) {
    uint16_t ha = __bfloat16_as_ushort(__float2bfloat16_rn(a));
    uint16_t hb = __bfloat16_as_ushort(__float2bfloat16_rn(b));
    return (uint32_t)ha | ((uint32_t)hb << 16);
}
__device__ __forceinline__ float residf(float f) {
    return f - __bfloat162float(__float2bfloat16_rn(f));
}

#define LDSM4(r0, r1, r2, r3, addr)                                            \
    asm volatile("ldmatrix.sync.aligned.m8n8.x4.shared.b16 {%0,%1,%2,%3}, [%4];" \
                 : "=r"(r0), "=r"(r1), "=r"(r2), "=r"(r3) : "r"(addr))

#define MMA16816(cc, a, b0, b1)                                                \
    asm volatile("mma.sync.aligned.m16n8k16.row.col.f32.bf16.bf16.f32 "        \
                 "{%0,%1,%2,%3}, {%4,%5,%6,%7}, {%8,%9}, {%0,%1,%2,%3};"       \
                 : "+f"(cc[0]), "+f"(cc[1]), "+f"(cc[2]), "+f"(cc[3])          \
                 : "r"(a[0]), "r"(a[1]), "r"(a[2]), "r"(a[3]), "r"(b0), "r"(b1))

// ---------------- CSR build -------------------------------------------------
__global__ void k_zero_cnt() {
    int i = blockIdx.x * blockDim.x + threadIdx.x;
    if (i < N_NODES) g_cnt[i] = 0;
}

__global__ void k_hist(const int* __restrict__ dst) {
    for (int e = blockIdx.x * blockDim.x + threadIdx.x; e < N_EDGES;
         e += gridDim.x * blockDim.x)
        atomicAdd(&g_cnt[dst[e]], 1);
}

// decomposed scan: block-local pass
__global__ void k_scan_blk() {
    int i = blockIdx.x * 1024 + threadIdx.x;
    int lane = threadIdx.x & 31;
    int wid  = threadIdx.x >> 5;
    int v = (i < N_NODES) ? g_cnt[i] : 0;
    int x = v;
#pragma unroll
    for (int o = 1; o < 32; o <<= 1) {
        int t = __shfl_up_sync(0xffffffffu, x, o);
        if (lane >= o) x += t;
    }
    __shared__ int wsum[32];
    if (lane == 31) wsum[wid] = x;
    __syncthreads();
    if (wid == 0) {
        int w = wsum[lane];
#pragma unroll
        for (int o = 1; o < 32; o <<= 1) {
            int t = __shfl_up_sync(0xffffffffu, w, o);
            if (lane >= o) w += t;
        }
        wsum[lane] = w;
    }
    __syncthreads();
    int excl = x - v + (wid ? wsum[wid - 1] : 0);
    if (i < N_NODES) g_off[i] = excl;
    if (threadIdx.x == 1023) g_blksum[blockIdx.x] = excl + v;
}

// scan of the 98 block totals (1 block, 128 threads)
__global__ void k_scan_top() {
    int t = threadIdx.x;
    int lane = t & 31;
    int wid  = t >> 5;
    int v = (t < SCAN_BLKS) ? g_blksum[t] : 0;
    int x = v;
#pragma unroll
    for (int o = 1; o < 32; o <<= 1) {
        int u = __shfl_up_sync(0xffffffffu, x, o);
        if (lane >= o) x += u;
    }
    __shared__ int wsum[4];
    if (lane == 31) wsum[wid] = x;
    __syncthreads();
    int add = 0;
    for (int w = 0; w < wid; w++) add += wsum[w];
    if (t < SCAN_BLKS) g_blkpfx[t] = x - v + add;
}

// apply block offsets
__global__ void k_scan_add() {
    int i = blockIdx.x * 1024 + threadIdx.x;
    if (i < N_NODES) {
        int o = g_off[i] + g_blkpfx[blockIdx.x];
        g_off[i] = o;
        g_cur[i] = o;
    }
}

__global__ void k_scatter(const int* __restrict__ src, const int* __restrict__ dst) {
    for (int e = blockIdx.x * blockDim.x + threadIdx.x; e < N_EDGES;
         e += gridDim.x * blockDim.x) {
        int d = dst[e];
        int p = atomicAdd(&g_cur[d], 1);
        g_csr[p] = src[e];
    }
}

// ---------------- weight hi/lo split ----------------------------------------
__global__ void k_convw(const float* __restrict__ W1l, const float* __restrict__ W1r,
                        const float* __restrict__ W2l, const float* __restrict__ W2r) {
    int i = blockIdx.x * blockDim.x + threadIdx.x;   // 0 .. 4*16384-1
    const float* srcs[4] = {W1l, W1r, W2l, W2r};
    float v = srcs[i >> 14][i & 16383];
    __nv_bfloat16 h = __float2bfloat16_rn(v);
    g_wh[i] = h;
    g_wl[i] = __float2bfloat16_rn(v - __bfloat162float(h));
}

// ---------------- mean aggregation: one warp per destination node -----------
__global__ void k_aggregate(const float* __restrict__ feat, float* __restrict__ out) {
    int warp = (blockIdx.x * blockDim.x + threadIdx.x) >> 5;
    int lane = threadIdx.x & 31;
    if (warp >= N_NODES) return;
    int off = g_off[warp];
    int deg = g_cnt[warp];
    float4 acc = make_float4(0.f, 0.f, 0.f, 0.f);
    const float4* f4 = (const float4*)feat;
    for (int i = 0; i < deg; i++) {
        int s = g_csr[off + i];
        float4 v = f4[(size_t)s * 32 + lane];
        acc.x += v.x; acc.y += v.y; acc.z += v.z; acc.w += v.w;
    }
    float inv = 1.0f / (float)max(deg, 1);
    acc.x *= inv; acc.y *= inv; acc.z *= inv; acc.w *= inv;
    ((float4*)out)[(size_t)warp * 32 + lane] = acc;
}

// ---------------- tensor-core dual GEMM -------------------------------------
// out[row,col] = sum_k A1[row,k]*Wa[col,k] + sum_k A2[row,k]*Wb[col,k] (+bias, relu?)
// bf16 hi/lo split: 3 MMAs per logical product (drops lo*lo, err ~2^-16).
__global__ __launch_bounds__(GT, 2)
void k_gemm(const float* __restrict__ A1, const float* __restrict__ A2,
            int w1idx, int w2idx, const float* __restrict__ bias,
            float* __restrict__ out, int do_relu)
{
    __shared__ __align__(16) __nv_bfloat16 sAh[BM * 24];
    __shared__ __align__(16) __nv_bfloat16 sAl[BM * 24];
    __shared__ __align__(16) __nv_bfloat16 sBh[BM * 24];
    __shared__ __align__(16) __nv_bfloat16 sBl[BM * 24];
    __shared__ float sbias[D];

    int tid  = threadIdx.x;
    int lane = tid & 31;
    int warp = tid >> 5;
    int warp_m = warp & 3;
    int warp_n = warp >> 2;
    int rowBase = blockIdx.x * BM;

    if (tid < D) sbias[tid] = bias[tid];

    int lrow  = tid >> 1;
    int lhalf = tid & 1;

    int ldrow = lane & 15;
    int ldoff = (lane >> 4) * 16;
    uint32_t aoff = (uint32_t)((warp_m * 32 + ldrow) * 48 + ldoff);
    uint32_t boff = (uint32_t)((warp_n * 64 + ldrow) * 48 + ldoff);
    uint32_t sAh_b = (uint32_t)__cvta_generic_to_shared(sAh);
    uint32_t sAl_b = (uint32_t)__cvta_generic_to_shared(sAl);
    uint32_t sBh_b = (uint32_t)__cvta_generic_to_shared(sBh);
    uint32_t sBl_b = (uint32_t)__cvta_generic_to_shared(sBl);

    float c[2][8][4];
#pragma unroll
    for (int mt = 0; mt < 2; mt++)
#pragma unroll
        for (int nc = 0; nc < 8; nc++)
#pragma unroll
            for (int r = 0; r < 4; r++) c[mt][nc][r] = 0.f;

    int grow = rowBase + lrow;
    bool rowOk = grow < N_NODES;

#pragma unroll 1
    for (int ph = 0; ph < 2; ph++) {
        const float* A = ph ? A2 : A1;
        const __nv_bfloat16* Wh = g_wh + (size_t)(ph ? w2idx : w1idx) * D * D;
        const __nv_bfloat16* Wl = g_wl + (size_t)(ph ? w2idx : w1idx) * D * D;

#pragma unroll 1
        for (int kb = 0; kb < D; kb += 16) {
            __syncthreads();
            float v0 = 0.f, v1 = 0.f, v2 = 0.f, v3 = 0.f;
            float v4 = 0.f, v5 = 0.f, v6 = 0.f, v7 = 0.f;
            if (rowOk) {
                const float* ap = A + (size_t)grow * D + kb + lhalf * 8;
                float4 f0 = *(const float4*)ap;
                float4 f1 = *(const float4*)(ap + 4);
                v0 = f0.x; v1 = f0.y; v2 = f0.z; v3 = f0.w;
                v4 = f1.x; v5 = f1.y; v6 = f1.z; v7 = f1.w;
            }
            {
                uint4 h = make_uint4(packbf(v0, v1), packbf(v2, v3),
                                     packbf(v4, v5), packbf(v6, v7));
                uint4 l = make_uint4(packbf(residf(v0), residf(v1)),
                                     packbf(residf(v2), residf(v3)),
                                     packbf(residf(v4), residf(v5)),
                                     packbf(residf(v6), residf(v7)));
                *(uint4*)(sAh + lrow * 24 + lhalf * 8) = h;
                *(uint4*)(sAl + lrow * 24 + lhalf * 8) = l;
            }
            {
                uint4 wh = *(const uint4*)(Wh + (size_t)lrow * D + kb + lhalf * 8);
                uint4 wl = *(const uint4*)(Wl + (size_t)lrow * D + kb + lhalf * 8);
                *(uint4*)(sBh + lrow * 24 + lhalf * 8) = wh;
                *(uint4*)(sBl + lrow * 24 + lhalf * 8) = wl;
            }
            __syncthreads();

            uint32_t ah[2][4], al[2][4];
            LDSM4(ah[0][0], ah[0][1], ah[0][2], ah[0][3], sAh_b + aoff);
            LDSM4(ah[1][0], ah[1][1], ah[1][2], ah[1][3], sAh_b + aoff + 16 * 48);
            LDSM4(al[0][0], al[0][1], al[0][2], al[0][3], sAl_b + aoff);
            LDSM4(al[1][0], al[1][1], al[1][2], al[1][3], sAl_b + aoff + 16 * 48);

#pragma unroll
            for (int ng = 0; ng < 4; ng++) {
                uint32_t bh[4], bl[4];
                LDSM4(bh[0], bh[1], bh[2], bh[3], sBh_b + boff + ng * 16 * 48);
                LDSM4(bl[0], bl[1], bl[2], bl[3], sBl_b + boff + ng * 16 * 48);
#pragma unroll
                for (int mt = 0; mt < 2; mt++) {
#pragma unroll
                    for (int sub = 0; sub < 2; sub++) {
                        float* cc = c[mt][ng * 2 + sub];
                        MMA16816(cc, ah[mt], bh[sub], bh[sub + 2]);
                        MMA16816(cc, ah[mt], bl[sub], bl[sub + 2]);
                        MMA16816(cc, al[mt], bh[sub], bh[sub + 2]);
                    }
                }
            }
        }
    }
    __syncthreads();

    int g = lane >> 2;
    int q = (lane & 3) * 2;
#pragma unroll
    for (int mt = 0; mt < 2; mt++) {
        int r0 = rowBase + warp_m * 32 + mt * 16 + g;
#pragma unroll
        for (int nc = 0; nc < 8; nc++) {
            int col = warp_n * 64 + nc * 8 + q;
            float b0 = sbias[col], b1 = sbias[col + 1];
            float* cc = c[mt][nc];
            float o0 = cc[0] + b0, o1 = cc[1] + b1;
            float o2 = cc[2] + b0, o3 = cc[3] + b1;
            if (do_relu) {
                o0 = fmaxf(o0, 0.f); o1 = fmaxf(o1, 0.f);
                o2 = fmaxf(o2, 0.f); o3 = fmaxf(o3, 0.f);
            }
            if (r0 < N_NODES) {
                float2 w = make_float2(o0, o1);
                *(float2*)(out + (size_t)r0 * D + col) = w;
            }
            if (r0 + 8 < N_NODES) {
                float2 w = make_float2(o2, o3);
                *(float2*)(out + (size_t)(r0 + 8) * D + col) = w;
            }
        }
    }
}

// ---------------- classifier: out = z @ Wc^T + bc ---------------------------
__global__ __launch_bounds__(256)
void k_classifier(const float* __restrict__ z, const float* __restrict__ Wc,
                  const float* __restrict__ bc, float* __restrict__ out)
{
    __shared__ float sW[DOUT][132];
    __shared__ float sb[DOUT];
    int tid = threadIdx.x;
    for (int i = tid; i < DOUT * D; i += 256) sW[i >> 7][i & 127] = Wc[i];
    if (tid < DOUT) sb[tid] = bc[tid];
    __syncthreads();

    int col = tid & 15;
    int row = blockIdx.x * 16 + (tid >> 4);
    if (row >= N_NODES) return;
    const float4* zr = (const float4*)(z + (size_t)row * D);
    float acc = 0.f;
#pragma unroll
    for (int k = 0; k < D / 4; k++) {
        float4 zv = zr[k];
        float4 wv = *(const float4*)&sW[col][k * 4];
        acc += zv.x * wv.x + zv.y * wv.y + zv.z * wv.z + zv.w * wv.w;
    }
    out[(size_t)row * DOUT + col] = acc + sb[col];
}

// ---------------- launch ----------------------------------------------------
extern "C" void kernel_launch(void* const* d_in, const int* in_sizes, int n_in,
                              void* d_out, int out_size)
{
    const float* x   = (const float*)d_in[0];
    const int*   ei  = (const int*)d_in[1];
    const float* W1l = (const float*)d_in[2];
    const float* b1l = (const float*)d_in[3];
    const float* W1r = (const float*)d_in[4];
    const float* W2l = (const float*)d_in[5];
    const float* b2l = (const float*)d_in[6];
    const float* W2r = (const float*)d_in[7];
    const float* Wc  = (const float*)d_in[8];
    const float* bc  = (const float*)d_in[9];
    float* out = (float*)d_out;

    const int* src = ei;
    const int* dst = ei + N_EDGES;

    float *agg, *h;
    cudaGetSymbolAddress((void**)&agg, g_agg);
    cudaGetSymbolAddress((void**)&h, g_h);

    // CSR build + weight split
    k_zero_cnt<<<(N_NODES + 1023) / 1024, 1024>>>();
    k_convw<<<(4 * D * D) / 256, 256>>>(W1l, W1r, W2l, W2r);
    k_hist<<<2048, 256>>>(dst);
    k_scan_blk<<<SCAN_BLKS, 1024>>>();
    k_scan_top<<<1, 128>>>();
    k_scan_add<<<SCAN_BLKS, 1024>>>();
    k_scatter<<<2048, 256>>>(src, dst);

    // layer 1
    k_aggregate<<<(N_NODES * 32 + 255) / 256, 256>>>(x, agg);
    k_gemm<<<GEMM_BLOCKS, GT>>>(agg, x, 0, 1, b1l, h, 1);

    // layer 2 (z written in-place into agg) + classifier
    k_aggregate<<<(N_NODES * 32 + 255) / 256, 256>>>(h, agg);
    k_gemm<<<GEMM_BLOCKS, GT>>>(agg, h, 2, 3, b2l, agg, 0);
    k_classifier<<<(N_NODES + 15) / 16, 256>>>(agg, Wc, bc, out);
}

// round 4
// speedup vs baseline: 2.8399x; 1.5556x over previous
#include <cuda_runtime.h>
#include <cuda_bf16.h>
#include <cstdint>

#define N_NODES 100000
#define N_EDGES 1600000
#define D 128
#define DOUT 16

#define BM 128
#define GT 256
#define GEMM_BLOCKS ((N_NODES + BM - 1) / BM)
#define SCAN_BLKS ((N_NODES + 1023) / 1024)   // 98

// ---------------- scratch (static device globals) ---------------------------
__device__ float g_agg[(size_t)N_NODES * D];   // layer-1 aggregation out
__device__ float g_h[(size_t)N_NODES * D];     // hidden activations
__device__ float g_pq[(size_t)N_NODES * 32];   // p (cols 0-15) and q (cols 16-31)
__device__ int   g_cnt[N_NODES];
__device__ int   g_off[N_NODES];
__device__ int   g_cur[N_NODES];
__device__ int   g_csr[N_EDGES];
__device__ int   g_blksum[SCAN_BLKS];
__device__ int   g_blkpfx[SCAN_BLKS];
__device__ __nv_bfloat16 g_wh[2 * D * D];      // W1l, W1r hi parts
__device__ __nv_bfloat16 g_wl[2 * D * D];      // W1l, W1r lo parts
__device__ __nv_bfloat16 g_wsh[32 * D];        // stacked [Wcl; Wcr] hi
__device__ __nv_bfloat16 g_wsl[32 * D];        // stacked [Wcl; Wcr] lo
__device__ float g_bco[DOUT];                  // Wc@b2l + bc

// ---------------- helpers ---------------------------------------------------
__device__ __forceinline__ uint32_t packbf(float a, float b) {
    uint16_t ha = __bfloat16_as_ushort(__float2bfloat16_rn(a));
    uint16_t hb = __bfloat16_as_ushort(__float2bfloat16_rn(b));
    return (uint32_t)ha | ((uint32_t)hb << 16);
}
__device__ __forceinline__ float residf(float f) {
    return f - __bfloat162float(__float2bfloat16_rn(f));
}

#define LDSM4(r0, r1, r2, r3, addr)                                            \
    asm volatile("ldmatrix.sync.aligned.m8n8.x4.shared.b16 {%0,%1,%2,%3}, [%4];" \
                 : "=r"(r0), "=r"(r1), "=r"(r2), "=r"(r3) : "r"(addr))

#define MMA16816(cc, a, b0, b1)                                                \
    asm volatile("mma.sync.aligned.m16n8k16.row.col.f32.bf16.bf16.f32 "        \
                 "{%0,%1,%2,%3}, {%4,%5,%6,%7}, {%8,%9}, {%0,%1,%2,%3};"       \
                 : "+f"(cc[0]), "+f"(cc[1]), "+f"(cc[2]), "+f"(cc[3])          \
                 : "r"(a[0]), "r"(a[1]), "r"(a[2]), "r"(a[3]), "r"(b0), "r"(b1))

// ---------------- CSR build -------------------------------------------------
__global__ void k_zero_cnt() {
    int i = blockIdx.x * blockDim.x + threadIdx.x;
    if (i < N_NODES) g_cnt[i] = 0;
}

__global__ void k_hist(const int* __restrict__ dst) {
    for (int e = blockIdx.x * blockDim.x + threadIdx.x; e < N_EDGES;
         e += gridDim.x * blockDim.x)
        atomicAdd(&g_cnt[dst[e]], 1);
}

__global__ void k_scan_blk() {
    int i = blockIdx.x * 1024 + threadIdx.x;
    int lane = threadIdx.x & 31;
    int wid  = threadIdx.x >> 5;
    int v = (i < N_NODES) ? g_cnt[i] : 0;
    int x = v;
#pragma unroll
    for (int o = 1; o < 32; o <<= 1) {
        int t = __shfl_up_sync(0xffffffffu, x, o);
        if (lane >= o) x += t;
    }
    __shared__ int wsum[32];
    if (lane == 31) wsum[wid] = x;
    __syncthreads();
    if (wid == 0) {
        int w = wsum[lane];
#pragma unroll
        for (int o = 1; o < 32; o <<= 1) {
            int t = __shfl_up_sync(0xffffffffu, w, o);
            if (lane >= o) w += t;
        }
        wsum[lane] = w;
    }
    __syncthreads();
    int excl = x - v + (wid ? wsum[wid - 1] : 0);
    if (i < N_NODES) g_off[i] = excl;
    if (threadIdx.x == 1023) g_blksum[blockIdx.x] = excl + v;
}

__global__ void k_scan_top() {
    int t = threadIdx.x;
    int lane = t & 31;
    int wid  = t >> 5;
    int v = (t < SCAN_BLKS) ? g_blksum[t] : 0;
    int x = v;
#pragma unroll
    for (int o = 1; o < 32; o <<= 1) {
        int u = __shfl_up_sync(0xffffffffu, x, o);
        if (lane >= o) x += u;
    }
    __shared__ int wsum[4];
    if (lane == 31) wsum[wid] = x;
    __syncthreads();
    int add = 0;
    for (int w = 0; w < wid; w++) add += wsum[w];
    if (t < SCAN_BLKS) g_blkpfx[t] = x - v + add;
}

__global__ void k_scan_add() {
    int i = blockIdx.x * 1024 + threadIdx.x;
    if (i < N_NODES) {
        int o = g_off[i] + g_blkpfx[blockIdx.x];
        g_off[i] = o;
        g_cur[i] = o;
    }
}

__global__ void k_scatter(const int* __restrict__ src, const int* __restrict__ dst) {
    for (int e = blockIdx.x * blockDim.x + threadIdx.x; e < N_EDGES;
         e += gridDim.x * blockDim.x) {
        int d = dst[e];
        int p = atomicAdd(&g_cur[d], 1);
        g_csr[p] = src[e];
    }
}

// ---------------- weight prep -----------------------------------------------
__global__ void k_convw(const float* __restrict__ W1l, const float* __restrict__ W1r) {
    int i = blockIdx.x * blockDim.x + threadIdx.x;   // 0 .. 2*16384-1
    const float* srcs[2] = {W1l, W1r};
    float v = srcs[i >> 14][i & 16383];
    __nv_bfloat16 h = __float2bfloat16_rn(v);
    g_wh[i] = h;
    g_wl[i] = __float2bfloat16_rn(v - __bfloat162float(h));
}

// compose Wcl = Wc@W2l, Wcr = Wc@W2r (stacked 32x128), bco = Wc@b2l + bc
__global__ void k_compose(const float* __restrict__ Wc, const float* __restrict__ W2l,
                          const float* __restrict__ W2r, const float* __restrict__ b2l,
                          const float* __restrict__ bc) {
    int idx = blockIdx.x * blockDim.x + threadIdx.x;   // 0..4095
    int which = idx >> 11;            // 0 => Wcl, 1 => Wcr
    int o = (idx >> 7) & 15;
    int k = idx & 127;
    const float* W2 = which ? W2r : W2l;
    float s = 0.f;
#pragma unroll 8
    for (int j = 0; j < D; j++)
        s += Wc[o * D + j] * W2[j * D + k];
    int row = which * 16 + o;
    __nv_bfloat16 hi = __float2bfloat16_rn(s);
    g_wsh[row * D + k] = hi;
    g_wsl[row * D + k] = __float2bfloat16_rn(s - __bfloat162float(hi));
    if (which == 0 && k == 0) {
        float b = bc[o];
        for (int j = 0; j < D; j++) b += Wc[o * D + j] * b2l[j];
        g_bco[o] = b;
    }
}

// ---------------- mean aggregation (layer 1): warp per node -----------------
__global__ void k_aggregate(const float* __restrict__ feat, float* __restrict__ out) {
    int warp = (blockIdx.x * blockDim.x + threadIdx.x) >> 5;
    int lane = threadIdx.x & 31;
    if (warp >= N_NODES) return;
    int off = g_off[warp];
    int deg = g_cnt[warp];
    float4 acc = make_float4(0.f, 0.f, 0.f, 0.f);
    const float4* f4 = (const float4*)feat;
    for (int i = 0; i < deg; i++) {
        int s = g_csr[off + i];
        float4 v = f4[(size_t)s * 32 + lane];
        acc.x += v.x; acc.y += v.y; acc.z += v.z; acc.w += v.w;
    }
    float inv = 1.0f / (float)max(deg, 1);
    acc.x *= inv; acc.y *= inv; acc.z *= inv; acc.w *= inv;
    ((float4*)out)[(size_t)warp * 32 + lane] = acc;
}

// ---------------- tensor-core dual GEMM (layer 1, N=128) --------------------
__global__ __launch_bounds__(GT, 2)
void k_gemm(const float* __restrict__ A1, const float* __restrict__ A2,
            int w1idx, int w2idx, const float* __restrict__ bias,
            float* __restrict__ out, int do_relu)
{
    __shared__ __align__(16) __nv_bfloat16 sAh[BM * 24];
    __shared__ __align__(16) __nv_bfloat16 sAl[BM * 24];
    __shared__ __align__(16) __nv_bfloat16 sBh[BM * 24];
    __shared__ __align__(16) __nv_bfloat16 sBl[BM * 24];
    __shared__ float sbias[D];

    int tid  = threadIdx.x;
    int lane = tid & 31;
    int warp = tid >> 5;
    int warp_m = warp & 3;
    int warp_n = warp >> 2;
    int rowBase = blockIdx.x * BM;

    if (tid < D) sbias[tid] = bias[tid];

    int lrow  = tid >> 1;
    int lhalf = tid & 1;

    int ldrow = lane & 15;
    int ldoff = (lane >> 4) * 16;
    uint32_t aoff = (uint32_t)((warp_m * 32 + ldrow) * 48 + ldoff);
    uint32_t boff = (uint32_t)((warp_n * 64 + ldrow) * 48 + ldoff);
    uint32_t sAh_b = (uint32_t)__cvta_generic_to_shared(sAh);
    uint32_t sAl_b = (uint32_t)__cvta_generic_to_shared(sAl);
    uint32_t sBh_b = (uint32_t)__cvta_generic_to_shared(sBh);
    uint32_t sBl_b = (uint32_t)__cvta_generic_to_shared(sBl);

    float c[2][8][4];
#pragma unroll
    for (int mt = 0; mt < 2; mt++)
#pragma unroll
        for (int nc = 0; nc < 8; nc++)
#pragma unroll
            for (int r = 0; r < 4; r++) c[mt][nc][r] = 0.f;

    int grow = rowBase + lrow;
    bool rowOk = grow < N_NODES;

#pragma unroll 1
    for (int ph = 0; ph < 2; ph++) {
        const float* A = ph ? A2 : A1;
        const __nv_bfloat16* Wh = g_wh + (size_t)(ph ? w2idx : w1idx) * D * D;
        const __nv_bfloat16* Wl = g_wl + (size_t)(ph ? w2idx : w1idx) * D * D;

#pragma unroll 1
        for (int kb = 0; kb < D; kb += 16) {
            __syncthreads();
            float v0 = 0.f, v1 = 0.f, v2 = 0.f, v3 = 0.f;
            float v4 = 0.f, v5 = 0.f, v6 = 0.f, v7 = 0.f;
            if (rowOk) {
                const float* ap = A + (size_t)grow * D + kb + lhalf * 8;
                float4 f0 = *(const float4*)ap;
                float4 f1 = *(const float4*)(ap + 4);
                v0 = f0.x; v1 = f0.y; v2 = f0.z; v3 = f0.w;
                v4 = f1.x; v5 = f1.y; v6 = f1.z; v7 = f1.w;
            }
            {
                uint4 h = make_uint4(packbf(v0, v1), packbf(v2, v3),
                                     packbf(v4, v5), packbf(v6, v7));
                uint4 l = make_uint4(packbf(residf(v0), residf(v1)),
                                     packbf(residf(v2), residf(v3)),
                                     packbf(residf(v4), residf(v5)),
                                     packbf(residf(v6), residf(v7)));
                *(uint4*)(sAh + lrow * 24 + lhalf * 8) = h;
                *(uint4*)(sAl + lrow * 24 + lhalf * 8) = l;
            }
            {
                uint4 wh = *(const uint4*)(Wh + (size_t)lrow * D + kb + lhalf * 8);
                uint4 wl = *(const uint4*)(Wl + (size_t)lrow * D + kb + lhalf * 8);
                *(uint4*)(sBh + lrow * 24 + lhalf * 8) = wh;
                *(uint4*)(sBl + lrow * 24 + lhalf * 8) = wl;
            }
            __syncthreads();

            uint32_t ah[2][4], al[2][4];
            LDSM4(ah[0][0], ah[0][1], ah[0][2], ah[0][3], sAh_b + aoff);
            LDSM4(ah[1][0], ah[1][1], ah[1][2], ah[1][3], sAh_b + aoff + 16 * 48);
            LDSM4(al[0][0], al[0][1], al[0][2], al[0][3], sAl_b + aoff);
            LDSM4(al[1][0], al[1][1], al[1][2], al[1][3], sAl_b + aoff + 16 * 48);

#pragma unroll
            for (int ng = 0; ng < 4; ng++) {
                uint32_t bh[4], bl[4];
                LDSM4(bh[0], bh[1], bh[2], bh[3], sBh_b + boff + ng * 16 * 48);
                LDSM4(bl[0], bl[1], bl[2], bl[3], sBl_b + boff + ng * 16 * 48);
#pragma unroll
                for (int mt = 0; mt < 2; mt++) {
#pragma unroll
                    for (int sub = 0; sub < 2; sub++) {
                        float* cc = c[mt][ng * 2 + sub];
                        MMA16816(cc, ah[mt], bh[sub], bh[sub + 2]);
                        MMA16816(cc, ah[mt], bl[sub], bl[sub + 2]);
                        MMA16816(cc, al[mt], bh[sub], bh[sub + 2]);
                    }
                }
            }
        }
    }
    __syncthreads();

    int g = lane >> 2;
    int q = (lane & 3) * 2;
#pragma unroll
    for (int mt = 0; mt < 2; mt++) {
        int r0 = rowBase + warp_m * 32 + mt * 16 + g;
#pragma unroll
        for (int nc = 0; nc < 8; nc++) {
            int col = warp_n * 64 + nc * 8 + q;
            float b0 = sbias[col], b1 = sbias[col + 1];
            float* cc = c[mt][nc];
            float o0 = cc[0] + b0, o1 = cc[1] + b1;
            float o2 = cc[2] + b0, o3 = cc[3] + b1;
            if (do_relu) {
                o0 = fmaxf(o0, 0.f); o1 = fmaxf(o1, 0.f);
                o2 = fmaxf(o2, 0.f); o3 = fmaxf(o3, 0.f);
            }
            if (r0 < N_NODES) {
                float2 w = make_float2(o0, o1);
                *(float2*)(out + (size_t)r0 * D + col) = w;
            }
            if (r0 + 8 < N_NODES) {
                float2 w = make_float2(o2, o3);
                *(float2*)(out + (size_t)(r0 + 8) * D + col) = w;
            }
        }
    }
}

// ---------------- layer-2 composed GEMM: pq = h @ [Wcl;Wcr]^T (N=32) --------
__global__ __launch_bounds__(GT, 2)
void k_gemm16(const float* __restrict__ A, float* __restrict__ pq)
{
    __shared__ __align__(16) __nv_bfloat16 sAh[BM * 24];
    __shared__ __align__(16) __nv_bfloat16 sAl[BM * 24];
    __shared__ __align__(16) __nv_bfloat16 sBh[32 * 24];
    __shared__ __align__(16) __nv_bfloat16 sBl[32 * 24];

    int tid  = threadIdx.x;
    int lane = tid & 31;
    int warp = tid >> 5;          // 8 warps x 16 rows
    int rowBase = blockIdx.x * BM;

    int lrow  = tid >> 1;
    int lhalf = tid & 1;

    int ldrow = lane & 15;
    int ldoff = (lane >> 4) * 16;
    uint32_t aoff = (uint32_t)((warp * 16 + ldrow) * 48 + ldoff);
    uint32_t boff = (uint32_t)(ldrow * 48 + ldoff);
    uint32_t sAh_b = (uint32_t)__cvta_generic_to_shared(sAh);
    uint32_t sAl_b = (uint32_t)__cvta_generic_to_shared(sAl);
    uint32_t sBh_b = (uint32_t)__cvta_generic_to_shared(sBh);
    uint32_t sBl_b = (uint32_t)__cvta_generic_to_shared(sBl);

    float c[4][4];
#pragma unroll
    for (int nt = 0; nt < 4; nt++)
#pragma unroll
        for (int r = 0; r < 4; r++) c[nt][r] = 0.f;

    int grow = rowBase + lrow;
    bool rowOk = grow < N_NODES;

#pragma unroll 1
    for (int kb = 0; kb < D; kb += 16) {
        __syncthreads();
        float v0 = 0.f, v1 = 0.f, v2 = 0.f, v3 = 0.f;
        float v4 = 0.f, v5 = 0.f, v6 = 0.f, v7 = 0.f;
        if (rowOk) {
            const float* ap = A + (size_t)grow * D + kb + lhalf * 8;
            float4 f0 = *(const float4*)ap;
            float4 f1 = *(const float4*)(ap + 4);
            v0 = f0.x; v1 = f0.y; v2 = f0.z; v3 = f0.w;
            v4 = f1.x; v5 = f1.y; v6 = f1.z; v7 = f1.w;
        }
        {
            uint4 h = make_uint4(packbf(v0, v1), packbf(v2, v3),
                                 packbf(v4, v5), packbf(v6, v7));
            uint4 l = make_uint4(packbf(residf(v0), residf(v1)),
                                 packbf(residf(v2), residf(v3)),
                                 packbf(residf(v4), residf(v5)),
                                 packbf(residf(v6), residf(v7)));
            *(uint4*)(sAh + lrow * 24 + lhalf * 8) = h;
            *(uint4*)(sAl + lrow * 24 + lhalf * 8) = l;
        }
        if (tid < 64) {
            int brow = tid >> 1;
            int bh2  = tid & 1;
            uint4 wh = *(const uint4*)(g_wsh + (size_t)brow * D + kb + bh2 * 8);
            uint4 wl = *(const uint4*)(g_wsl + (size_t)brow * D + kb + bh2 * 8);
            *(uint4*)(sBh + brow * 24 + bh2 * 8) = wh;
            *(uint4*)(sBl + brow * 24 + bh2 * 8) = wl;
        }
        __syncthreads();

        uint32_t ah[4], al[4];
        LDSM4(ah[0], ah[1], ah[2], ah[3], sAh_b + aoff);
        LDSM4(al[0], al[1], al[2], al[3], sAl_b + aoff);

#pragma unroll
        for (int ng = 0; ng < 2; ng++) {
            uint32_t bh[4], bl[4];
            LDSM4(bh[0], bh[1], bh[2], bh[3], sBh_b + boff + ng * 16 * 48);
            LDSM4(bl[0], bl[1], bl[2], bl[3], sBl_b + boff + ng * 16 * 48);
#pragma unroll
            for (int sub = 0; sub < 2; sub++) {
                float* cc = c[ng * 2 + sub];
                MMA16816(cc, ah, bh[sub], bh[sub + 2]);
                MMA16816(cc, ah, bl[sub], bl[sub + 2]);
                MMA16816(cc, al, bh[sub], bh[sub + 2]);
            }
        }
    }

    int g = lane >> 2;
    int q = (lane & 3) * 2;
    int r0 = rowBase + warp * 16 + g;
#pragma unroll
    for (int nt = 0; nt < 4; nt++) {
        int col = nt * 8 + q;
        float* cc = c[nt];
        if (r0 < N_NODES)
            *(float2*)(pq + (size_t)r0 * 32 + col) = make_float2(cc[0], cc[1]);
        if (r0 + 8 < N_NODES)
            *(float2*)(pq + (size_t)(r0 + 8) * 32 + col) = make_float2(cc[2], cc[3]);
    }
}

// ---------------- layer-2 aggregation + final output (16-dim) ---------------
// out[n] = mean_{j in N(n)} p[j] + q[n] + bco   (4 lanes per node, float4 each)
__global__ void k_agg_out(float* __restrict__ out) {
    int t = blockIdx.x * blockDim.x + threadIdx.x;
    int node = t >> 2;
    int sub  = t & 3;
    if (node >= N_NODES) return;
    int off = g_off[node];
    int deg = g_cnt[node];
    const float4* pq4 = (const float4*)g_pq;
    float4 acc = make_float4(0.f, 0.f, 0.f, 0.f);
    for (int i = 0; i < deg; i++) {
        int s = g_csr[off + i];
        float4 v = pq4[(size_t)s * 8 + sub];           // p part (cols 0-15)
        acc.x += v.x; acc.y += v.y; acc.z += v.z; acc.w += v.w;
    }
    float inv = 1.0f / (float)max(deg, 1);
    float4 qv = pq4[(size_t)node * 8 + 4 + sub];       // q part (cols 16-31)
    float4 bv = *(const float4*)(g_bco + sub * 4);
    float4 o;
    o.x = acc.x * inv + qv.x + bv.x;
    o.y = acc.y * inv + qv.y + bv.y;
    o.z = acc.z * inv + qv.z + bv.z;
    o.w = acc.w * inv + qv.w + bv.w;
    ((float4*)out)[(size_t)node * 4 + sub] = o;
}

// ---------------- launch ----------------------------------------------------
extern "C" void kernel_launch(void* const* d_in, const int* in_sizes, int n_in,
                              void* d_out, int out_size)
{
    const float* x   = (const float*)d_in[0];
    const int*   ei  = (const int*)d_in[1];
    const float* W1l = (const float*)d_in[2];
    const float* b1l = (const float*)d_in[3];
    const float* W1r = (const float*)d_in[4];
    const float* W2l = (const float*)d_in[5];
    const float* b2l = (const float*)d_in[6];
    const float* W2r = (const float*)d_in[7];
    const float* Wc  = (const float*)d_in[8];
    const float* bc  = (const float*)d_in[9];
    float* out = (float*)d_out;

    const int* src = ei;
    const int* dst = ei + N_EDGES;

    float *agg, *h, *pq;
    cudaGetSymbolAddress((void**)&agg, g_agg);
    cudaGetSymbolAddress((void**)&h, g_h);
    cudaGetSymbolAddress((void**)&pq, g_pq);

    // CSR build + weight prep
    k_zero_cnt<<<(N_NODES + 1023) / 1024, 1024>>>();
    k_convw<<<(2 * D * D) / 256, 256>>>(W1l, W1r);
    k_compose<<<8, 512>>>(Wc, W2l, W2r, b2l, bc);
    k_hist<<<2048, 256>>>(dst);
    k_scan_blk<<<SCAN_BLKS, 1024>>>();
    k_scan_top<<<1, 128>>>();
    k_scan_add<<<SCAN_BLKS, 1024>>>();
    k_scatter<<<2048, 256>>>(src, dst);

    // layer 1
    k_aggregate<<<(N_NODES * 32 + 255) / 256, 256>>>(x, agg);
    k_gemm<<<GEMM_BLOCKS, GT>>>(agg, x, 0, 1, b1l, h, 1);

    // layer 2 (composed through classifier)
    k_gemm16<<<GEMM_BLOCKS, GT>>>(h, pq);
    k_agg_out<<<(N_NODES * 4 + 255) / 256, 256>>>(out);
}